// round 4
// baseline (speedup 1.0000x reference)
#include <cuda_runtime.h>

// GarNet: B=256, V=1024, F=16, P=16, A=8, NF=32
// out[b,v,n] = mask(v) * ( sum_a ew[v,a] * M[b,a,n] + b_out[n] )
//   ew[v,a]  = mask(v) * 2^(-(data[v]·W_s + b_s)[a])
//   agg[a,p] = (1/V) sum_v ew[v,a] * (data[v]·W_flr + b_flr)[p]
//   M[a,n]   = sum_p agg[a,p] * W_out[a*P+p, n]
//
// Pipeline:
//   K1 (8x256 x128t):  streaming per-vertex feat/ew -> scratch (f32x2 packed FMA)
//   Kr (32x256 x128t): partial agg reduction over 32-vertex tiles
//   Km (256 x128t):    partials -> agg -> M
//   K2 (8x256 x128t):  out = mask*(ew @ M + b_out), M in registers

#define NB   256
#define NV   1024
#define NFEA 16
#define NP   16
#define NA   8
#define NOUT 32

#define K1S  8      // K1/K2 v-splits
#define K1V  128
#define KRS  32     // Kr v-splits
#define KRV  32

__device__ float g_ew[NB * NV * NA];          // 8 MB
__device__ float g_feat[NB * NV * NP];        // 8 MB
__device__ float g_part[NB * KRS * 128];      // 4 MB
__device__ float g_M[NB * NA * NOUT];         // 256 KB

#define FMA_F32X2(d, a, b, c) \
    asm("fma.rn.f32x2 %0, %1, %2, %3;" : "=l"(d) : "l"(a), "l"(b), "l"(c))
#define PACK2_SAME(out, x) \
    asm("mov.b64 %0, {%1, %1};" : "=l"(out) : "r"(__float_as_uint(x)))
#define UNPACK2(lo, hi, in) \
    asm("mov.b64 {%0, %1}, %2;" : "=r"(lo), "=r"(hi) : "l"(in))

// ==================== K1: streaming feat + ew ====================
__global__ void __launch_bounds__(128, 8)
garnet_k1(const float* __restrict__ data,
          const int*   __restrict__ num_vertex,
          const float* __restrict__ W_flr,
          const float* __restrict__ b_flr,
          const float* __restrict__ W_s,
          const float* __restrict__ b_s)
{
    __shared__ float Wf_sh[256];
    __shared__ float Ws_sh[128];
    __shared__ float bf_sh[16];
    __shared__ float bs_sh[8];

    const int t = threadIdx.x;
    const int s = blockIdx.x;
    const int b = blockIdx.y;
    const int v = s * K1V + t;

    Wf_sh[t]       = W_flr[t];
    Wf_sh[t + 128] = W_flr[t + 128];
    Ws_sh[t]       = W_s[t];
    if (t < 16) bf_sh[t] = b_flr[t];
    if (t < 8)  bs_sh[t] = b_s[t];
    const int nv = num_vertex[b];
    __syncthreads();

    const float4* data4 = reinterpret_cast<const float4*>(data)
                        + ((size_t)b * NV + v) * (NFEA / 4);
    float4 q0 = data4[0], q1 = data4[1], q2 = data4[2], q3 = data4[3];
    float dv[16] = {q0.x,q0.y,q0.z,q0.w, q1.x,q1.y,q1.z,q1.w,
                    q2.x,q2.y,q2.z,q2.w, q3.x,q3.y,q3.z,q3.w};

    // packed accumulators along p / a (pairs of adjacent outputs)
    unsigned long long f2[8], sd2[4];
    {
        const unsigned long long* bf2 = reinterpret_cast<const unsigned long long*>(bf_sh);
        const unsigned long long* bs2 = reinterpret_cast<const unsigned long long*>(bs_sh);
        #pragma unroll
        for (int j = 0; j < 8; ++j) f2[j] = bf2[j];
        #pragma unroll
        for (int j = 0; j < 4; ++j) sd2[j] = bs2[j];
    }

    const ulonglong2* Wf2 = reinterpret_cast<const ulonglong2*>(Wf_sh);
    const ulonglong2* Ws2 = reinterpret_cast<const ulonglong2*>(Ws_sh);

    #pragma unroll
    for (int k = 0; k < 16; ++k) {
        unsigned long long xp;
        PACK2_SAME(xp, dv[k]);
        const ulonglong2 w0 = Wf2[k*4+0], w1 = Wf2[k*4+1];
        const ulonglong2 w2 = Wf2[k*4+2], w3 = Wf2[k*4+3];
        FMA_F32X2(f2[0], xp, w0.x, f2[0]);
        FMA_F32X2(f2[1], xp, w0.y, f2[1]);
        FMA_F32X2(f2[2], xp, w1.x, f2[2]);
        FMA_F32X2(f2[3], xp, w1.y, f2[3]);
        FMA_F32X2(f2[4], xp, w2.x, f2[4]);
        FMA_F32X2(f2[5], xp, w2.y, f2[5]);
        FMA_F32X2(f2[6], xp, w3.x, f2[6]);
        FMA_F32X2(f2[7], xp, w3.y, f2[7]);
        const ulonglong2 u0 = Ws2[k*2+0], u1 = Ws2[k*2+1];
        FMA_F32X2(sd2[0], xp, u0.x, sd2[0]);
        FMA_F32X2(sd2[1], xp, u0.y, sd2[1]);
        FMA_F32X2(sd2[2], xp, u1.x, sd2[2]);
        FMA_F32X2(sd2[3], xp, u1.y, sd2[3]);
    }

    // ew = mask * 2^(-dist)
    const bool m = (v < nv);
    float ew[8];
    #pragma unroll
    for (int j = 0; j < 4; ++j) {
        unsigned int lo, hi;
        UNPACK2(lo, hi, sd2[j]);
        ew[2*j]   = m ? exp2f(-__uint_as_float(lo)) : 0.0f;
        ew[2*j+1] = m ? exp2f(-__uint_as_float(hi)) : 0.0f;
    }

    float4* ewg4 = reinterpret_cast<float4*>(g_ew + ((size_t)b * NV + v) * NA);
    ewg4[0] = make_float4(ew[0], ew[1], ew[2], ew[3]);
    ewg4[1] = make_float4(ew[4], ew[5], ew[6], ew[7]);

    // feat: packed pairs store directly
    ulonglong2* fg2 = reinterpret_cast<ulonglong2*>(g_feat + ((size_t)b * NV + v) * NP);
    fg2[0] = make_ulonglong2(f2[0], f2[1]);
    fg2[1] = make_ulonglong2(f2[2], f2[3]);
    fg2[2] = make_ulonglong2(f2[4], f2[5]);
    fg2[3] = make_ulonglong2(f2[6], f2[7]);
}

// ==================== Kr: partial agg over 32-vertex tiles ====================
__global__ void __launch_bounds__(128)
garnet_kr()
{
    __shared__ float ew_sh[KRV * NA];     // [v][a]
    __shared__ float ft_sh[KRV * NP];     // [v][p]

    const int t = threadIdx.x;
    const int s = blockIdx.x;
    const int b = blockIdx.y;
    const size_t vbase = (size_t)b * NV + s * KRV;

    {
        const float4* esrc = reinterpret_cast<const float4*>(g_ew + vbase * NA);
        const float4* fsrc = reinterpret_cast<const float4*>(g_feat + vbase * NP);
        if (t < 64) reinterpret_cast<float4*>(ew_sh)[t] = esrc[t];
        reinterpret_cast<float4*>(ft_sh)[t] = fsrc[t];
    }
    __syncthreads();

    // thread t -> (a = t>>4, p = t&15); reduce over 32 vertices
    const int a = t >> 4, p = t & 15;
    float acc = 0.f;
    #pragma unroll
    for (int v = 0; v < KRV; ++v)
        acc += ew_sh[v * NA + a] * ft_sh[v * NP + p];
    g_part[((size_t)b * KRS + s) * 128 + t] = acc;
}

// ==================== Km: partials -> agg -> M ====================
__global__ void __launch_bounds__(128)
garnet_km(const float* __restrict__ W_out)
{
    __shared__ float agg_sh[128];
    __shared__ float Wo_sh[NA * NP * NOUT];

    const int t = threadIdx.x;
    const int b = blockIdx.x;

    {
        const float4* src = reinterpret_cast<const float4*>(W_out);
        float4* dst = reinterpret_cast<float4*>(Wo_sh);
        #pragma unroll
        for (int i = 0; i < 8; ++i) dst[t + i * 128] = src[t + i * 128];
    }

    float acc = 0.f;
    #pragma unroll
    for (int sp = 0; sp < KRS; ++sp)
        acc += g_part[((size_t)b * KRS + sp) * 128 + t];
    agg_sh[t] = acc * (1.0f / (float)NV);
    __syncthreads();

    #pragma unroll
    for (int e = t; e < 256; e += 128) {
        const int a = e >> 5, n = e & 31;
        float mm = 0.f;
        #pragma unroll
        for (int p = 0; p < 16; ++p)
            mm += agg_sh[a * 16 + p] * Wo_sh[(a * 16 + p) * 32 + n];
        g_M[b * 256 + e] = mm;
    }
}

// ==================== K2: output ====================
__global__ void __launch_bounds__(128)
garnet_k2(const int*   __restrict__ num_vertex,
          const float* __restrict__ b_out,
          float*       __restrict__ out)
{
    __shared__ float4 ew4_sh[K1V * 2];
    __shared__ float4 M4_sh[64];

    const int t  = threadIdx.x;
    const int s  = blockIdx.x;
    const int b  = blockIdx.y;
    const int ng = t & 7;
    const int vl = t >> 3;

    {
        const float4* src = reinterpret_cast<const float4*>(g_ew)
                          + ((size_t)b * NV + s * K1V) * 2;
        ew4_sh[t]       = src[t];
        ew4_sh[t + 128] = src[t + 128];
        if (t < 64)
            M4_sh[t] = reinterpret_cast<const float4*>(g_M + b * 256)[t];
    }
    const int nv = num_vertex[b];
    const float4 bo = reinterpret_cast<const float4*>(b_out)[ng];
    __syncthreads();

    float4 Mr[8];
    #pragma unroll
    for (int a = 0; a < 8; ++a) Mr[a] = M4_sh[a * 8 + ng];

    float4* out4 = reinterpret_cast<float4*>(out)
                 + ((size_t)b * NV + s * K1V) * (NOUT / 4);
    const float4 z = make_float4(0.f, 0.f, 0.f, 0.f);

    #pragma unroll
    for (int k = 0; k < 8; ++k) {
        const int v = vl + k * 16;
        const float4 e0 = ew4_sh[v * 2];
        const float4 e1 = ew4_sh[v * 2 + 1];

        float4 acc = bo;
        acc.x += e0.x*Mr[0].x; acc.y += e0.x*Mr[0].y; acc.z += e0.x*Mr[0].z; acc.w += e0.x*Mr[0].w;
        acc.x += e0.y*Mr[1].x; acc.y += e0.y*Mr[1].y; acc.z += e0.y*Mr[1].z; acc.w += e0.y*Mr[1].w;
        acc.x += e0.z*Mr[2].x; acc.y += e0.z*Mr[2].y; acc.z += e0.z*Mr[2].z; acc.w += e0.z*Mr[2].w;
        acc.x += e0.w*Mr[3].x; acc.y += e0.w*Mr[3].y; acc.z += e0.w*Mr[3].z; acc.w += e0.w*Mr[3].w;
        acc.x += e1.x*Mr[4].x; acc.y += e1.x*Mr[4].y; acc.z += e1.x*Mr[4].z; acc.w += e1.x*Mr[4].w;
        acc.x += e1.y*Mr[5].x; acc.y += e1.y*Mr[5].y; acc.z += e1.y*Mr[5].z; acc.w += e1.y*Mr[5].w;
        acc.x += e1.z*Mr[6].x; acc.y += e1.z*Mr[6].y; acc.z += e1.z*Mr[6].z; acc.w += e1.z*Mr[6].w;
        acc.x += e1.w*Mr[7].x; acc.y += e1.w*Mr[7].y; acc.z += e1.w*Mr[7].z; acc.w += e1.w*Mr[7].w;

        out4[v * 8 + ng] = (s * K1V + v < nv) ? acc : z;
    }
}

extern "C" void kernel_launch(void* const* d_in, const int* in_sizes, int n_in,
                              void* d_out, int out_size)
{
    const float* data       = (const float*)d_in[0];
    const int*   num_vertex = (const int*)  d_in[1];
    const float* W_flr      = (const float*)d_in[2];
    const float* b_flr      = (const float*)d_in[3];
    const float* W_s        = (const float*)d_in[4];
    const float* b_s        = (const float*)d_in[5];
    const float* W_out      = (const float*)d_in[6];
    const float* b_out      = (const float*)d_in[7];
    float*       out        = (float*)d_out;

    (void)in_sizes; (void)n_in; (void)out_size;

    dim3 g1(K1S, NB), gr(KRS, NB);
    garnet_k1<<<g1, 128>>>(data, num_vertex, W_flr, b_flr, W_s, b_s);
    garnet_kr<<<gr, 128>>>();
    garnet_km<<<NB, 128>>>(W_out);
    garnet_k2<<<g1, 128>>>(num_vertex, b_out, out);
}

// round 5
// speedup vs baseline: 1.4594x; 1.4594x over previous
#include <cuda_runtime.h>

// GarNet: B=256, V=1024, F=16, P=16, A=8, NF=32
// out[b,v,n] = mask(v) * ( sum_a ew[v,a] * M[b,a,n] + b_out[n] )
//   ew[v,a]  = mask(v) * 2^(-(data[v]·W_s + b_s)[a])
//   agg[a,p] = (1/V) sum_v ew[v,a] * (data[v]·W_flr + b_flr)[p]
//   M[a,n]   = sum_p agg[a,p] * W_out[a*P+p, n]
//
// Pipeline (round-3 structure, K1 rebuilt):
//   K1 (4x256 x128t): 2 vertices/thread feat+ew (f32x2), ew->scratch,
//                     block partial agg over 256 vertices.
//   Km (256 x128t):   4 partials -> agg -> M.
//   K2 (8x256 x128t): out = mask*(ew @ M + b_out), M in registers.

#define NB   256
#define NV   1024
#define NFEA 16
#define NP   16
#define NA   8
#define NOUT 32

#define K1S  4      // K1 v-splits (256 vertices per block)
#define K1V  256
#define K2S  8
#define K2V  128

#define RSTRIDE 260   // 256 + 4 (stride ≡ 4 mod 32 -> conflict-free rows)

__device__ float g_ew[NB * NV * NA];          // 8 MB
__device__ float g_part[NB * K1S * 128];      // 512 KB
__device__ float g_M[NB * NA * NOUT];         // 256 KB

#define FMA_F32X2(d, a, b, c) \
    asm("fma.rn.f32x2 %0, %1, %2, %3;" : "=l"(d) : "l"(a), "l"(b), "l"(c))
#define PACK2_SAME(out, x) \
    asm("mov.b64 %0, {%1, %1};" : "=l"(out) : "r"(__float_as_uint(x)))
#define UNPACK2(lo, hi, in) \
    asm("mov.b64 {%0, %1}, %2;" : "=r"(lo), "=r"(hi) : "l"(in))

// ==================== K1 ====================
__global__ void __launch_bounds__(128)
garnet_k1(const float* __restrict__ data,
          const int*   __restrict__ num_vertex,
          const float* __restrict__ W_flr,
          const float* __restrict__ b_flr,
          const float* __restrict__ W_s,
          const float* __restrict__ b_s)
{
    __shared__ float Wf_sh[256];
    __shared__ float Ws_sh[128];
    __shared__ float bf_sh[16];
    __shared__ float bs_sh[8];
    __shared__ float red[(NA + NP) * RSTRIDE];   // rows 0..7 ew[a][v], 8..23 feat[p][v]

    const int t = threadIdx.x;
    const int s = blockIdx.x;      // 0..3
    const int b = blockIdx.y;
    const int v0 = s * K1V + t;    // vertex 0
    const int v1 = v0 + 128;       // vertex 1

    Wf_sh[t]       = W_flr[t];
    Wf_sh[t + 128] = W_flr[t + 128];
    Ws_sh[t]       = W_s[t];
    if (t < 16) bf_sh[t] = b_flr[t];
    if (t < 8)  bs_sh[t] = b_s[t];
    const int nv = num_vertex[b];
    __syncthreads();

    const float4* d40 = reinterpret_cast<const float4*>(data) + ((size_t)b * NV + v0) * 4;
    const float4* d41 = reinterpret_cast<const float4*>(data) + ((size_t)b * NV + v1) * 4;

    // packed accumulators (pairs along p / a)
    unsigned long long f2a[8], f2b[8], sd2a[4], sd2b[4];
    {
        const unsigned long long* bf2 = reinterpret_cast<const unsigned long long*>(bf_sh);
        const unsigned long long* bs2 = reinterpret_cast<const unsigned long long*>(bs_sh);
        #pragma unroll
        for (int j = 0; j < 8; ++j) { f2a[j] = bf2[j]; f2b[j] = bf2[j]; }
        #pragma unroll
        for (int j = 0; j < 4; ++j) { sd2a[j] = bs2[j]; sd2b[j] = bs2[j]; }
    }

    const ulonglong2* Wf2 = reinterpret_cast<const ulonglong2*>(Wf_sh);
    const ulonglong2* Ws2 = reinterpret_cast<const ulonglong2*>(Ws_sh);

    // two k-chunks of 8 to limit live registers
    #pragma unroll
    for (int c = 0; c < 2; ++c) {
        float4 qa0 = d40[c*2+0], qa1 = d40[c*2+1];
        float4 qb0 = d41[c*2+0], qb1 = d41[c*2+1];
        float xa[8] = {qa0.x,qa0.y,qa0.z,qa0.w, qa1.x,qa1.y,qa1.z,qa1.w};
        float xb[8] = {qb0.x,qb0.y,qb0.z,qb0.w, qb1.x,qb1.y,qb1.z,qb1.w};

        #pragma unroll
        for (int kk = 0; kk < 8; ++kk) {
            const int k = c * 8 + kk;
            unsigned long long xpa, xpb;
            PACK2_SAME(xpa, xa[kk]);
            PACK2_SAME(xpb, xb[kk]);
            const ulonglong2 w0 = Wf2[k*4+0], w1 = Wf2[k*4+1];
            const ulonglong2 w2 = Wf2[k*4+2], w3 = Wf2[k*4+3];
            FMA_F32X2(f2a[0], xpa, w0.x, f2a[0]);  FMA_F32X2(f2b[0], xpb, w0.x, f2b[0]);
            FMA_F32X2(f2a[1], xpa, w0.y, f2a[1]);  FMA_F32X2(f2b[1], xpb, w0.y, f2b[1]);
            FMA_F32X2(f2a[2], xpa, w1.x, f2a[2]);  FMA_F32X2(f2b[2], xpb, w1.x, f2b[2]);
            FMA_F32X2(f2a[3], xpa, w1.y, f2a[3]);  FMA_F32X2(f2b[3], xpb, w1.y, f2b[3]);
            FMA_F32X2(f2a[4], xpa, w2.x, f2a[4]);  FMA_F32X2(f2b[4], xpb, w2.x, f2b[4]);
            FMA_F32X2(f2a[5], xpa, w2.y, f2a[5]);  FMA_F32X2(f2b[5], xpb, w2.y, f2b[5]);
            FMA_F32X2(f2a[6], xpa, w3.x, f2a[6]);  FMA_F32X2(f2b[6], xpb, w3.x, f2b[6]);
            FMA_F32X2(f2a[7], xpa, w3.y, f2a[7]);  FMA_F32X2(f2b[7], xpb, w3.y, f2b[7]);
            const ulonglong2 u0 = Ws2[k*2+0], u1 = Ws2[k*2+1];
            FMA_F32X2(sd2a[0], xpa, u0.x, sd2a[0]);  FMA_F32X2(sd2b[0], xpb, u0.x, sd2b[0]);
            FMA_F32X2(sd2a[1], xpa, u0.y, sd2a[1]);  FMA_F32X2(sd2b[1], xpb, u0.y, sd2b[1]);
            FMA_F32X2(sd2a[2], xpa, u1.x, sd2a[2]);  FMA_F32X2(sd2b[2], xpb, u1.x, sd2b[2]);
            FMA_F32X2(sd2a[3], xpa, u1.y, sd2a[3]);  FMA_F32X2(sd2b[3], xpb, u1.y, sd2b[3]);
        }
    }

    // ew = mask * 2^(-dist); stage to smem + global
    {
        const bool ma = (v0 < nv), mb = (v1 < nv);
        float ewa[8], ewb[8];
        #pragma unroll
        for (int j = 0; j < 4; ++j) {
            unsigned int lo, hi;
            UNPACK2(lo, hi, sd2a[j]);
            ewa[2*j]   = ma ? exp2f(-__uint_as_float(lo)) : 0.0f;
            ewa[2*j+1] = ma ? exp2f(-__uint_as_float(hi)) : 0.0f;
            UNPACK2(lo, hi, sd2b[j]);
            ewb[2*j]   = mb ? exp2f(-__uint_as_float(lo)) : 0.0f;
            ewb[2*j+1] = mb ? exp2f(-__uint_as_float(hi)) : 0.0f;
        }
        float4* e4a = reinterpret_cast<float4*>(g_ew + ((size_t)b * NV + v0) * NA);
        float4* e4b = reinterpret_cast<float4*>(g_ew + ((size_t)b * NV + v1) * NA);
        e4a[0] = make_float4(ewa[0], ewa[1], ewa[2], ewa[3]);
        e4a[1] = make_float4(ewa[4], ewa[5], ewa[6], ewa[7]);
        e4b[0] = make_float4(ewb[0], ewb[1], ewb[2], ewb[3]);
        e4b[1] = make_float4(ewb[4], ewb[5], ewb[6], ewb[7]);

        #pragma unroll
        for (int a = 0; a < 8; ++a) {
            red[a * RSTRIDE + t]       = ewa[a];
            red[a * RSTRIDE + t + 128] = ewb[a];
        }
        #pragma unroll
        for (int j = 0; j < 8; ++j) {
            unsigned int lo, hi;
            UNPACK2(lo, hi, f2a[j]);
            red[(8 + 2*j)     * RSTRIDE + t] = __uint_as_float(lo);
            red[(8 + 2*j + 1) * RSTRIDE + t] = __uint_as_float(hi);
            UNPACK2(lo, hi, f2b[j]);
            red[(8 + 2*j)     * RSTRIDE + t + 128] = __uint_as_float(lo);
            red[(8 + 2*j + 1) * RSTRIDE + t + 128] = __uint_as_float(hi);
        }
    }
    __syncthreads();

    // block reduction: thread t -> (a = t>>4, p = t&15), dot over 256 vertices
    {
        const int a = t >> 4, p = t & 15;
        const float4* er = reinterpret_cast<const float4*>(&red[a * RSTRIDE]);
        const float4* fr = reinterpret_cast<const float4*>(&red[(8 + p) * RSTRIDE]);
        float4 acc = make_float4(0.f, 0.f, 0.f, 0.f);
        #pragma unroll
        for (int k = 0; k < K1V / 4; ++k) {
            const float4 e = er[k];
            const float4 ff = fr[k];
            acc.x += e.x * ff.x; acc.y += e.y * ff.y;
            acc.z += e.z * ff.z; acc.w += e.w * ff.w;
        }
        g_part[((size_t)b * K1S + s) * 128 + t] = acc.x + acc.y + acc.z + acc.w;
    }
}

// ==================== Km ====================
__global__ void __launch_bounds__(128)
garnet_km(const float* __restrict__ W_out)
{
    __shared__ float agg_sh[128];
    __shared__ float Wo_sh[NA * NP * NOUT];

    const int t = threadIdx.x;
    const int b = blockIdx.x;

    {
        const float4* src = reinterpret_cast<const float4*>(W_out);
        float4* dst = reinterpret_cast<float4*>(Wo_sh);
        #pragma unroll
        for (int i = 0; i < 8; ++i) dst[t + i * 128] = src[t + i * 128];
    }

    float acc = 0.f;
    #pragma unroll
    for (int sp = 0; sp < K1S; ++sp)
        acc += g_part[((size_t)b * K1S + sp) * 128 + t];
    agg_sh[t] = acc * (1.0f / (float)NV);
    __syncthreads();

    #pragma unroll
    for (int e = t; e < 256; e += 128) {
        const int a = e >> 5, n = e & 31;
        float mm = 0.f;
        #pragma unroll
        for (int p = 0; p < 16; ++p)
            mm += agg_sh[a * 16 + p] * Wo_sh[(a * 16 + p) * 32 + n];
        g_M[b * 256 + e] = mm;
    }
}

// ==================== K2 ====================
__global__ void __launch_bounds__(128)
garnet_k2(const int*   __restrict__ num_vertex,
          const float* __restrict__ b_out,
          float*       __restrict__ out)
{
    __shared__ float4 ew4_sh[K2V * 2];
    __shared__ float4 M4_sh[64];

    const int t  = threadIdx.x;
    const int s  = blockIdx.x;
    const int b  = blockIdx.y;
    const int ng = t & 7;
    const int vl = t >> 3;

    {
        const float4* src = reinterpret_cast<const float4*>(g_ew)
                          + ((size_t)b * NV + s * K2V) * 2;
        ew4_sh[t]       = src[t];
        ew4_sh[t + 128] = src[t + 128];
        if (t < 64)
            M4_sh[t] = reinterpret_cast<const float4*>(g_M + b * 256)[t];
    }
    const int nv = num_vertex[b];
    const float4 bo = reinterpret_cast<const float4*>(b_out)[ng];
    __syncthreads();

    float4 Mr[8];
    #pragma unroll
    for (int a = 0; a < 8; ++a) Mr[a] = M4_sh[a * 8 + ng];

    float4* out4 = reinterpret_cast<float4*>(out)
                 + ((size_t)b * NV + s * K2V) * (NOUT / 4);
    const float4 z = make_float4(0.f, 0.f, 0.f, 0.f);

    #pragma unroll
    for (int k = 0; k < 8; ++k) {
        const int v = vl + k * 16;
        const float4 e0 = ew4_sh[v * 2];
        const float4 e1 = ew4_sh[v * 2 + 1];

        float4 acc = bo;
        acc.x += e0.x*Mr[0].x; acc.y += e0.x*Mr[0].y; acc.z += e0.x*Mr[0].z; acc.w += e0.x*Mr[0].w;
        acc.x += e0.y*Mr[1].x; acc.y += e0.y*Mr[1].y; acc.z += e0.y*Mr[1].z; acc.w += e0.y*Mr[1].w;
        acc.x += e0.z*Mr[2].x; acc.y += e0.z*Mr[2].y; acc.z += e0.z*Mr[2].z; acc.w += e0.z*Mr[2].w;
        acc.x += e0.w*Mr[3].x; acc.y += e0.w*Mr[3].y; acc.z += e0.w*Mr[3].z; acc.w += e0.w*Mr[3].w;
        acc.x += e1.x*Mr[4].x; acc.y += e1.x*Mr[4].y; acc.z += e1.x*Mr[4].z; acc.w += e1.x*Mr[4].w;
        acc.x += e1.y*Mr[5].x; acc.y += e1.y*Mr[5].y; acc.z += e1.y*Mr[5].z; acc.w += e1.y*Mr[5].w;
        acc.x += e1.z*Mr[6].x; acc.y += e1.z*Mr[6].y; acc.z += e1.z*Mr[6].z; acc.w += e1.z*Mr[6].w;
        acc.x += e1.w*Mr[7].x; acc.y += e1.w*Mr[7].y; acc.z += e1.w*Mr[7].z; acc.w += e1.w*Mr[7].w;

        out4[v * 8 + ng] = (s * K2V + v < nv) ? acc : z;
    }
}

extern "C" void kernel_launch(void* const* d_in, const int* in_sizes, int n_in,
                              void* d_out, int out_size)
{
    const float* data       = (const float*)d_in[0];
    const int*   num_vertex = (const int*)  d_in[1];
    const float* W_flr      = (const float*)d_in[2];
    const float* b_flr      = (const float*)d_in[3];
    const float* W_s        = (const float*)d_in[4];
    const float* b_s        = (const float*)d_in[5];
    const float* W_out      = (const float*)d_in[6];
    const float* b_out      = (const float*)d_in[7];
    float*       out        = (float*)d_out;

    (void)in_sizes; (void)n_in; (void)out_size;

    dim3 g1(K1S, NB), g2(K2S, NB);
    garnet_k1<<<g1, 128>>>(data, num_vertex, W_flr, b_flr, W_s, b_s);
    garnet_km<<<NB, 128>>>(W_out);
    garnet_k2<<<g2, 128>>>(num_vertex, b_out, out);
}